// round 12
// baseline (speedup 1.0000x reference)
#include <cuda_runtime.h>
#include <math.h>
#include <stddef.h>

#define B 32
#define H 512
#define V 32000
#define T 64
#define GRID 128
#define NT 512
#define NTILE 250           /* 250 logits tiles of 128 vocab rows */
#define START_INDEX 1
#define XPAD 516            /* conflict-free 16B smem reads, lane = batch */
#define NCHUNK 32           /* logits k-chunks: 4 q (16 floats) each */
#define WSTRIDE 20          /* padded floats per row per chunk buffer */

typedef unsigned long long u64;

/* ------------------------- persistent device scratch ---------------------- */
__device__ float g_h0[2][B * H];
__device__ float g_c0[B * H];
__device__ float g_h1[2][B * H];
__device__ float g_c1[B * H];
__device__ float g_pre0[2048 * B];  /* ctx part of layer0 gates + b_ih + b_hh */
__device__ float g_pmax[NTILE * B];
__device__ float g_psum[NTILE * B];
__device__ u64   g_amax[2][B];      /* packed (sortable(max)<<32)|~idx, per parity */
__device__ float g_lsp[8][B];       /* distributed deterministic LSE partials */
__device__ int          g_cnt[16];  /* two-level barrier */
__device__ int          g_cnt_root;
__device__ volatile int g_gen;

__device__ __forceinline__ float sigf(float x) { return 1.0f / (1.0f + expf(-x)); }

/* packed fp32x2 FMA: d.lo += a.lo*b.lo ; d.hi += a.hi*b.hi */
__device__ __forceinline__ void fma2(u64& d, u64 a, u64 b) {
    asm("fma.rn.f32x2 %0, %1, %2, %0;" : "+l"(d) : "l"(a), "l"(b));
}
union F2U { u64 u; float2 f; };
__device__ __forceinline__ float f2sum(u64 v) { F2U t; t.u = v; return t.f.x + t.f.y; }

/* order-preserving float<->u32 transform */
__device__ __forceinline__ unsigned fsort(float x) {
    unsigned u = __float_as_uint(x);
    return u ^ ((unsigned)(((int)u) >> 31) | 0x80000000u);
}
__device__ __forceinline__ float funsort(unsigned s) {
    unsigned u = (s & 0x80000000u) ? (s ^ 0x80000000u) : ~s;
    return __uint_as_float(u);
}
__device__ __forceinline__ u64 packkey(float m, int idx) {
    return ((u64)fsort(m) << 32) | (u64)(~(unsigned)idx);
}

/* cp.async 16B, L1-bypass (.cg): GMEM -> SMEM without touching L1 */
__device__ __forceinline__ void cpa16(void* dst, const void* src) {
    unsigned d = (unsigned)__cvta_generic_to_shared(dst);
    asm volatile("cp.async.cg.shared.global [%0], [%1], 16;" :: "r"(d), "l"(src));
}
#define CP_COMMIT() asm volatile("cp.async.commit_group;")
#define CP_WAIT1()  asm volatile("cp.async.wait_group 1;")

/* grid barrier, two-level arrivals; replay-safe; all GRID blocks co-resident */
__device__ __forceinline__ void gridbar() {
    __syncthreads();
    if (threadIdx.x == 0) {
        int gen = g_gen;
        __threadfence();
        if (atomicAdd(&g_cnt[blockIdx.x >> 3], 1) == 7) {
            g_cnt[blockIdx.x >> 3] = 0;
            if (atomicAdd(&g_cnt_root, 1) == 15) {
                g_cnt_root = 0;
                __threadfence();
                g_gen = gen + 1;
            }
        }
        while (g_gen == gen) __nanosleep(32);
        __threadfence();
    }
    __syncthreads();
}

/* 4-row GEMM slice: acc[j] += W[row j][k-quarter] . x  (rows rs_u2 u2 apart) */
__device__ __forceinline__ void gemm4(u64* acc, const float* W, int rs_u2,
                                      const float* s_x, int kq, int lane) {
    const ulonglong2* xp = (const ulonglong2*)(s_x + lane * XPAD);
    const ulonglong2* wp = (const ulonglong2*)W;
#pragma unroll 4
    for (int q = kq * 32; q < kq * 32 + 32; q++) {
        ulonglong2 xv = xp[q];
        ulonglong2 w0 = wp[q], w1 = wp[rs_u2 + q], w2 = wp[2 * rs_u2 + q], w3 = wp[3 * rs_u2 + q];
        fma2(acc[0], w0.x, xv.x); fma2(acc[0], w0.y, xv.y);
        fma2(acc[1], w1.x, xv.x); fma2(acc[1], w1.y, xv.y);
        fma2(acc[2], w2.x, xv.x); fma2(acc[2], w2.y, xv.y);
        fma2(acc[3], w3.x, xv.x); fma2(acc[3], w3.y, xv.y);
    }
}

/* combine (m,s,idx) softmax partials; first-index tie rule */
__device__ __forceinline__ void comb(float& m, float& s, int& mi,
                                     float om, float os, int oi) {
    if (om > m || (om == m && oi < mi)) { s = s * expf(m - om) + os; m = om; mi = oi; }
    else                                { s += os * expf(om - m); }
}

/* ---------------------------------------------------------------------------
 * Whole decode, one persistent kernel. 128 blocks x 512 threads.
 * ------------------------------------------------------------------------- */
__global__ __launch_bounds__(NT) void k_all(
    const float* __restrict__ ctx,  const float* __restrict__ emb,
    const float* __restrict__ Wih0, const float* __restrict__ Whh0,
    const float* __restrict__ bih0, const float* __restrict__ bhh0,
    const float* __restrict__ Wih1, const float* __restrict__ Whh1,
    const float* __restrict__ bih1, const float* __restrict__ bhh1,
    const float* __restrict__ Wout, const float* __restrict__ bout,
    float* __restrict__ out)
{
    extern __shared__ float sm[];
    float* s_x    = sm;                       /* [32][XPAD] 16512 fl (also store overlay) */
    float* s_p    = s_x + 32 * XPAD;          /* [4][16][32] LSTM partials */
    float* s_rs   = s_p + 2048;               /* [16][32] LSE partial reduce */
    int*   s_tok  = (int*)(s_rs + 512);       /* [32] */
    float* s_fm   = (float*)(s_tok + 32);     /* [32] */
    float* s_lse  = s_fm + 32;                /* [32] */
    float* s_Rm   = s_lse + 32;               /* [512] logits warp partials */
    float* s_Rs   = s_Rm + 512;
    int*   s_Ri   = (int*)(s_Rs + 512);
    float* s_w    = (float*)(s_Ri + 512);     /* [2 halves][2 bufs][128*WSTRIDE] */

    int tid = threadIdx.x, blk = blockIdx.x;
    int w = tid >> 5, lane = tid & 31;

    /* ================= pre phase ================= */
    { int i = blk * NT + tid;
      if (i < B * H) { g_h0[0][i] = 0.f; g_h0[1][i] = 0.f; g_c0[i] = 0.f;
                       g_h1[0][i] = 0.f; g_h1[1][i] = 0.f; g_c1[i] = 0.f; } }
    if (blk == 0 && tid < 64) ((u64*)g_amax)[tid] = 0ull;   /* key 0 < any real key */
    for (int i = tid; i < B * 512; i += NT) {
        int b = i >> 9, k = i & 511;
        s_x[b * XPAD + k] = ctx[i];
    }
    __syncthreads();
    { int r = blk * 16 + w;
      const ulonglong2* wp = (const ulonglong2*)(Wih0 + (size_t)r * 1024 + 512);
      const ulonglong2* xp = (const ulonglong2*)(s_x + lane * XPAD);
      u64 a0 = 0, a1 = 0;
#pragma unroll 4
      for (int q = 0; q < 128; q++) {
          ulonglong2 a = wp[q], x = xp[q];
          fma2(a0, a.x, x.x); fma2(a1, a.y, x.y);
      }
      g_pre0[r * 32 + lane] = (f2sum(a0) + f2sum(a1)) + bih0[r] + bhh0[r];
    }
    gridbar();

    /* ================= decode loop ================= */
    for (int t = 0; t <= T; t++) {
        /* ---- prologue ---- */
        if (t > 0) {
            if (tid < 32) {
                u64 key = g_amax[(t - 1) & 1][tid];
                s_tok[tid] = (int)(~(unsigned)(key & 0xffffffffu));
                s_fm[tid]  = funsort((unsigned)(key >> 32));
            }
            __syncthreads();
            if (blk < 8) {      /* deterministic distributed LSE partials */
                int b = lane, g = w;
                float mb = s_fm[b];
                float s = 0.0f;
#pragma unroll
                for (int k = 0; k < 2; k++) {
                    int p = blk * 32 + g + 16 * k;
                    if (p < NTILE)
                        s += g_psum[p * 32 + b] * expf(g_pmax[p * 32 + b] - mb);
                }
                s_rs[g * 32 + b] = s;
                __syncthreads();
                if (tid < 32) {
                    float s2 = 0.0f;
                    for (int g2 = 0; g2 < 16; g2++) s2 += s_rs[g2 * 32 + tid];
                    g_lsp[blk][tid] = s2;
                }
            }
        } else {
            if (tid < 32) s_tok[tid] = START_INDEX;
            __syncthreads();
        }

        if (t == T) {
            gridbar();          /* publish g_lsp for T-1 */
            if (tid < 32) {
                float s2 = 0.0f;
#pragma unroll
                for (int k = 0; k < 8; k++) s2 += g_lsp[k][tid];
                s_lse[tid] = s_fm[tid] + logf(s2);
            }
            __syncthreads();
            int half = tid >> 8, th = tid & 255;
            int tile = blk + 128 * half;
            if (tile < NTILE) {
                int b = th >> 3, vl = (th & 7) * 16;
                float lv = s_lse[b];
                float* dst = &out[(size_t)b * ((size_t)T * V) + (size_t)(T - 1) * V
                                  + tile * 128 + vl];
#pragma unroll
                for (int c = 0; c < 4; c++) {
                    float4 vv = *(float4*)(dst + 4 * c);
                    vv.x -= lv; vv.y -= lv; vv.z -= lv; vv.w -= lv;
                    __stcs((float4*)(dst + 4 * c), vv);
                }
            }
            break;
        }

        int prev = t & 1, nxt = prev ^ 1;
        int rq = w >> 2, kq = w & 3, j0 = blk * 4;

        /* ---- lstm0 ---- */
        for (int i = tid; i < 32 * 128; i += NT) {
            int b = i >> 7, q = i & 127;
            *(float4*)(s_x + b * XPAD + 4 * q) =
                __ldcs((const float4*)(emb + (size_t)s_tok[b] * 512 + 4 * q));
        }
        __syncthreads();
        {
            u64 acc[4] = {0, 0, 0, 0};
            gemm4(acc, Wih0 + (size_t)(rq * 512 + j0) * 1024, 256, s_x, kq, lane);
            __syncthreads();
            for (int i = tid; i < 32 * 128; i += NT) {
                int b = i >> 7, q = i & 127;
                *(float4*)(s_x + b * XPAD + 4 * q) =
                    *(const float4*)(&g_h0[prev][b * 512 + 4 * q]);
            }
            __syncthreads();
            gemm4(acc, Whh0 + (size_t)(rq * 512 + j0) * 512, 128, s_x, kq, lane);
#pragma unroll
            for (int j = 0; j < 4; j++)
                s_p[(kq * 16 + rq * 4 + j) * 32 + lane] = f2sum(acc[j]);
            __syncthreads();
            if (tid < 128) {
                int jl = tid >> 5, b = tid & 31;
                int jg = j0 + jl;
                float gs[4];
#pragma unroll
                for (int g = 0; g < 4; g++) {
                    float s = 0.0f;
#pragma unroll
                    for (int k = 0; k < 4; k++) s += s_p[(k * 16 + g * 4 + jl) * 32 + b];
                    gs[g] = s + g_pre0[(g * 512 + jg) * 32 + b];
                }
                float c  = g_c0[b * 512 + jg];
                float cn = sigf(gs[1]) * c + sigf(gs[0]) * tanhf(gs[2]);
                float hn = sigf(gs[3]) * tanhf(cn);
                g_c0[b * 512 + jg] = cn;
                g_h0[nxt][b * 512 + jg] = hn;
            }
        }
        gridbar();

        /* reset amax parity consumed this prologue */
        if (blk == 0 && tid < 32) g_amax[(t - 1) & 1][tid] = 0ull;

        /* ---- lstm1 ---- */
        for (int i = tid; i < 32 * 128; i += NT) {
            int b = i >> 7, q = i & 127;
            *(float4*)(s_x + b * XPAD + 4 * q) =
                *(const float4*)(&g_h0[nxt][b * 512 + 4 * q]);
        }
        __syncthreads();
        {
            u64 acc[4] = {0, 0, 0, 0};
            gemm4(acc, Wih1 + (size_t)(rq * 512 + j0) * 512, 128, s_x, kq, lane);
            __syncthreads();
            for (int i = tid; i < 32 * 128; i += NT) {
                int b = i >> 7, q = i & 127;
                *(float4*)(s_x + b * XPAD + 4 * q) =
                    *(const float4*)(&g_h1[prev][b * 512 + 4 * q]);
            }
            __syncthreads();
            gemm4(acc, Whh1 + (size_t)(rq * 512 + j0) * 512, 128, s_x, kq, lane);
#pragma unroll
            for (int j = 0; j < 4; j++)
                s_p[(kq * 16 + rq * 4 + j) * 32 + lane] = f2sum(acc[j]);
            __syncthreads();
            if (tid < 128) {
                int jl = tid >> 5, b = tid & 31;
                int jg = j0 + jl;
                float gs[4];
#pragma unroll
                for (int g = 0; g < 4; g++) {
                    float s = 0.0f;
#pragma unroll
                    for (int k = 0; k < 4; k++) s += s_p[(k * 16 + g * 4 + jl) * 32 + b];
                    int rr = g * 512 + jg;
                    gs[g] = s + bih1[rr] + bhh1[rr];
                }
                float c  = g_c1[b * 512 + jg];
                float cn = sigf(gs[1]) * c + sigf(gs[0]) * tanhf(gs[2]);
                float hn = sigf(gs[3]) * tanhf(cn);
                g_c1[b * 512 + jg] = cn;
                g_h1[nxt][b * 512 + jg] = hn;
            }
        }
        gridbar();

        /* ---- logits: smem-staged Wout, double-buffered cp.async.cg ---- */
        for (int i = tid; i < 32 * 128; i += NT) {
            int b = i >> 7, q = i & 127;
            *(float4*)(s_x + b * XPAD + 4 * q) =
                *(const float4*)(&g_h1[nxt][b * 512 + 4 * q]);
        }
        if (t > 0 && tid < 32) {
            float s2 = 0.0f;
#pragma unroll
            for (int k = 0; k < 8; k++) s2 += g_lsp[k][tid];
            s_lse[tid] = s_fm[tid] + logf(s2);
        }
        __syncthreads();

        int half = tid >> 8, th = tid & 255;
        int tile = blk + 128 * half;
        bool act = (tile < NTILE);
        int vb = tile * 128;
        int vg = th >> 3, bg = th & 7;       /* thread tile 4v x 4b */
        float l[4][4];
        u64 a[4][4];
#pragma unroll
        for (int j = 0; j < 4; j++)
#pragma unroll
            for (int i = 0; i < 4; i++) a[j][i] = 0;

        /* prefetch chunk 0 */
        if (act) {
#pragma unroll
            for (int o = th; o < 512; o += 256) {
                int r = o >> 2, s = o & 3;
                cpa16(s_w + (half * 2 + 0) * (128 * WSTRIDE) + r * WSTRIDE + s * 4,
                      Wout + (size_t)(vb + r) * 512 + s * 4);
            }
        }
        CP_COMMIT();

        for (int c = 0; c < NCHUNK; c++) {
            /* prefetch chunk c+1 into other buffer */
            if (act && c + 1 < NCHUNK) {
#pragma unroll
                for (int o = th; o < 512; o += 256) {
                    int r = o >> 2, s = o & 3;
                    cpa16(s_w + (half * 2 + ((c + 1) & 1)) * (128 * WSTRIDE) + r * WSTRIDE + s * 4,
                          Wout + (size_t)(vb + r) * 512 + (c + 1) * 16 + s * 4);
                }
            }
            CP_COMMIT();
            CP_WAIT1();
            __syncthreads();
            if (act) {
                const float* wt = s_w + (half * 2 + (c & 1)) * (128 * WSTRIDE);
#pragma unroll
                for (int qm = 0; qm < 4; qm++) {
                    ulonglong2 hv[4], wv[4];
#pragma unroll
                    for (int i = 0; i < 4; i++)
                        hv[i] = *(const ulonglong2*)(s_x + (bg + 8 * i) * XPAD + (c * 4 + qm) * 4);
#pragma unroll
                    for (int j = 0; j < 4; j++)
                        wv[j] = *(const ulonglong2*)(wt + (vg + 32 * j) * WSTRIDE + qm * 4);
#pragma unroll
                    for (int j = 0; j < 4; j++)
#pragma unroll
                        for (int i = 0; i < 4; i++) {
                            fma2(a[j][i], wv[j].x, hv[i].x);
                            fma2(a[j][i], wv[j].y, hv[i].y);
                        }
                }
            }
            __syncthreads();
        }

        if (act) {
            float bj[4];
#pragma unroll
            for (int j = 0; j < 4; j++) bj[j] = bout[vb + vg + 32 * j];

            int lw = th & 31;
#pragma unroll
            for (int i = 0; i < 4; i++) {
                float m = -3.0e38f; int mi = 0;
#pragma unroll
                for (int j = 0; j < 4; j++) {
                    float lv = f2sum(a[j][i]) + bj[j];
                    l[i][j] = lv;
                    if (lv > m) { m = lv; mi = vb + vg + 32 * j; }
                }
                float s = 0.f;
#pragma unroll
                for (int j = 0; j < 4; j++) s += expf(l[i][j] - m);
#pragma unroll
                for (int off = 8; off <= 16; off <<= 1) {
                    float om = __shfl_xor_sync(0xffffffffu, m, off);
                    float os = __shfl_xor_sync(0xffffffffu, s, off);
                    int   oi = __shfl_xor_sync(0xffffffffu, mi, off);
                    comb(m, s, mi, om, os, oi);
                }
                if (lw < 8) {
                    int idx = half * 256 + (th >> 5) * 32 + bg * 4 + i;
                    s_Rm[idx] = m; s_Rs[idx] = s; s_Ri[idx] = mi;
                }
            }
        }
        __syncthreads();                     /* s_x free for overlay */

        float* s_ov = s_x + half * 4224;     /* [32][132] per half */
        if (act) {
#pragma unroll
            for (int i = 0; i < 4; i++)
#pragma unroll
                for (int j = 0; j < 4; j++)
                    s_ov[(bg + 8 * i) * 132 + vg + 32 * j] = l[i][j];
        }
        if (tid < 64) {                      /* per-tile combine + global argmax */
            int tl = tid >> 5, b = tid & 31;
            int t2 = blk + 128 * tl;
            if (t2 < NTILE) {
                int bg2 = b & 7, i2 = b >> 3;
                float m = -3.0e38f, s = 0.f; int mi = 0x7fffffff;
                for (int w2 = 0; w2 < 8; w2++) {
                    int idx = tl * 256 + w2 * 32 + bg2 * 4 + i2;
                    comb(m, s, mi, s_Rm[idx], s_Rs[idx], s_Ri[idx]);
                }
                g_pmax[t2 * 32 + b] = m;
                g_psum[t2 * 32 + b] = s;
                atomicMax(&g_amax[t & 1][b], packkey(m, mi));
            }
        }
        __syncthreads();

        if (act) {
            int b = th >> 3, vl = (th & 7) * 16;
            const float* src = s_ov + b * 132 + vl;
            float* dst = &out[(size_t)b * ((size_t)T * V) + (size_t)t * V + vb + vl];
#pragma unroll
            for (int c = 0; c < 4; c++)
                __stcs((float4*)(dst + 4 * c), *(const float4*)(src + 4 * c));
            if (t > 0) {                     /* normalize own tile of step t-1 */
                float lv = s_lse[b];
                float* pd = &out[(size_t)b * ((size_t)T * V) + (size_t)(t - 1) * V + vb + vl];
#pragma unroll
                for (int c = 0; c < 4; c++) {
                    float4 vv = __ldcs((const float4*)(pd + 4 * c));
                    vv.x -= lv; vv.y -= lv; vv.z -= lv; vv.w -= lv;
                    __stcs((float4*)(pd + 4 * c), vv);
                }
            }
        }
        gridbar();
    }
}

/* -------------------------------- launch ---------------------------------- */
#define SMEM_ALL ((32 * XPAD + 2048 + 512 + 32 * 3 + 512 * 3 + 4 * 128 * WSTRIDE) * 4)

extern "C" void kernel_launch(void* const* d_in, const int* in_sizes, int n_in,
                              void* d_out, int out_size) {
    const float* ctx  = (const float*)d_in[0];
    const float* emb  = (const float*)d_in[1];
    const float* Wih0 = (const float*)d_in[2];
    const float* Whh0 = (const float*)d_in[3];
    const float* bih0 = (const float*)d_in[4];
    const float* bhh0 = (const float*)d_in[5];
    const float* Wih1 = (const float*)d_in[6];
    const float* Whh1 = (const float*)d_in[7];
    const float* bih1 = (const float*)d_in[8];
    const float* bhh1 = (const float*)d_in[9];
    const float* Wout = (const float*)d_in[10];
    const float* bout = (const float*)d_in[11];
    float* out = (float*)d_out;

    cudaFuncSetAttribute(k_all, cudaFuncAttributeMaxDynamicSharedMemorySize, SMEM_ALL);
    k_all<<<GRID, NT, SMEM_ALL>>>(ctx, emb, Wih0, Whh0, bih0, bhh0,
                                  Wih1, Whh1, bih1, bhh1, Wout, bout, out);
}

// round 13
// speedup vs baseline: 1.1489x; 1.1489x over previous
#include <cuda_runtime.h>
#include <math.h>
#include <stddef.h>

#define B 32
#define H 512
#define V 32000
#define T 64
#define GRID 128
#define NT 512
#define NTILE 250           /* 250 logits tiles of 128 vocab rows */
#define START_INDEX 1
#define XPAD 516            /* conflict-free 16B smem reads, lane = batch */
#define NCHK 16             /* logits k-chunks: 8 q (32 floats) each */
#define WST 36              /* padded floats per row per chunk buffer */

typedef unsigned long long u64;

/* ------------------------- persistent device scratch ---------------------- */
__device__ float g_h0[2][B * H];
__device__ float g_c0[B * H];
__device__ float g_h1[2][B * H];
__device__ float g_c1[B * H];
__device__ float g_pre0[2048 * B];  /* ctx part of layer0 gates + b_ih + b_hh */
__device__ float g_pmax[NTILE * B];
__device__ float g_psum[NTILE * B];
__device__ u64   g_amax[2][B];      /* packed (sortable(max)<<32)|~idx, per parity */
__device__ float g_lsp[8][B];       /* distributed deterministic LSE partials */
__device__ int          g_cnt[16];  /* two-level barrier */
__device__ int          g_cnt_root;
__device__ volatile int g_gen;

__device__ __forceinline__ float sigf(float x) { return 1.0f / (1.0f + expf(-x)); }

/* packed fp32x2 FMA: d.lo += a.lo*b.lo ; d.hi += a.hi*b.hi */
__device__ __forceinline__ void fma2(u64& d, u64 a, u64 b) {
    asm("fma.rn.f32x2 %0, %1, %2, %0;" : "+l"(d) : "l"(a), "l"(b));
}
union F2U { u64 u; float2 f; };
__device__ __forceinline__ float f2sum(u64 v) { F2U t; t.u = v; return t.f.x + t.f.y; }

/* order-preserving float<->u32 transform */
__device__ __forceinline__ unsigned fsort(float x) {
    unsigned u = __float_as_uint(x);
    return u ^ ((unsigned)(((int)u) >> 31) | 0x80000000u);
}
__device__ __forceinline__ float funsort(unsigned s) {
    unsigned u = (s & 0x80000000u) ? (s ^ 0x80000000u) : ~s;
    return __uint_as_float(u);
}
__device__ __forceinline__ u64 packkey(float m, int idx) {
    return ((u64)fsort(m) << 32) | (u64)(~(unsigned)idx);
}

/* cp.async 16B, L1-bypass (.cg): GMEM -> SMEM without touching L1 */
__device__ __forceinline__ void cpa16(void* dst, const void* src) {
    unsigned d = (unsigned)__cvta_generic_to_shared(dst);
    asm volatile("cp.async.cg.shared.global [%0], [%1], 16;" :: "r"(d), "l"(src));
}
#define CP_COMMIT() asm volatile("cp.async.commit_group;" ::: "memory")
#define CP_WAIT1()  asm volatile("cp.async.wait_group 1;" ::: "memory")
#define BARH(id)    asm volatile("bar.sync %0, %1;" :: "r"(id), "r"(256) : "memory")

/* prefetch one 32-float k-chunk of a 128-row tile into buffer buf */
__device__ __forceinline__ void pf_chunk(float* s_w, int half, int buf,
                                         const float* Wout, int vb, int c, int th) {
#pragma unroll
    for (int k = 0; k < 4; k++) {
        int o = th + 256 * k;               /* 0..1023 */
        int r = o >> 3, s = o & 7;
        cpa16(s_w + (half * 3 + buf) * (128 * WST) + r * WST + s * 4,
              Wout + (size_t)(vb + r) * 512 + c * 32 + s * 4);
    }
}

/* grid barrier, two-level arrivals; replay-safe; all GRID blocks co-resident */
__device__ __forceinline__ void gridbar() {
    __syncthreads();
    if (threadIdx.x == 0) {
        int gen = g_gen;
        __threadfence();
        if (atomicAdd(&g_cnt[blockIdx.x >> 3], 1) == 7) {
            g_cnt[blockIdx.x >> 3] = 0;
            if (atomicAdd(&g_cnt_root, 1) == 15) {
                g_cnt_root = 0;
                __threadfence();
                g_gen = gen + 1;
            }
        }
        while (g_gen == gen) __nanosleep(32);
        __threadfence();
    }
    __syncthreads();
}

/* 4-row GEMM slice: acc[j] += W[row j][k-quarter] . x  (rows rs_u2 u2 apart) */
__device__ __forceinline__ void gemm4(u64* acc, const float* W, int rs_u2,
                                      const float* s_x, int kq, int lane) {
    const ulonglong2* xp = (const ulonglong2*)(s_x + lane * XPAD);
    const ulonglong2* wp = (const ulonglong2*)W;
#pragma unroll 4
    for (int q = kq * 32; q < kq * 32 + 32; q++) {
        ulonglong2 xv = xp[q];
        ulonglong2 w0 = wp[q], w1 = wp[rs_u2 + q], w2 = wp[2 * rs_u2 + q], w3 = wp[3 * rs_u2 + q];
        fma2(acc[0], w0.x, xv.x); fma2(acc[0], w0.y, xv.y);
        fma2(acc[1], w1.x, xv.x); fma2(acc[1], w1.y, xv.y);
        fma2(acc[2], w2.x, xv.x); fma2(acc[2], w2.y, xv.y);
        fma2(acc[3], w3.x, xv.x); fma2(acc[3], w3.y, xv.y);
    }
}

/* combine (m,s,idx) softmax partials; first-index tie rule */
__device__ __forceinline__ void comb(float& m, float& s, int& mi,
                                     float om, float os, int oi) {
    if (om > m || (om == m && oi < mi)) { s = s * expf(m - om) + os; m = om; mi = oi; }
    else                                { s += os * expf(om - m); }
}

/* ---------------------------------------------------------------------------
 * Whole decode, one persistent kernel. 128 blocks x 512 threads.
 * ------------------------------------------------------------------------- */
__global__ __launch_bounds__(NT) void k_all(
    const float* __restrict__ ctx,  const float* __restrict__ emb,
    const float* __restrict__ Wih0, const float* __restrict__ Whh0,
    const float* __restrict__ bih0, const float* __restrict__ bhh0,
    const float* __restrict__ Wih1, const float* __restrict__ Whh1,
    const float* __restrict__ bih1, const float* __restrict__ bhh1,
    const float* __restrict__ Wout, const float* __restrict__ bout,
    float* __restrict__ out)
{
    extern __shared__ float sm[];
    float* s_x    = sm;                       /* [32][XPAD] 16512 fl (also store overlay) */
    float* s_p    = s_x + 32 * XPAD;          /* [4][16][32] LSTM partials */
    float* s_rs   = s_p + 2048;               /* [16][32] LSE partial reduce */
    int*   s_tok  = (int*)(s_rs + 512);       /* [32] */
    float* s_fm   = (float*)(s_tok + 32);     /* [32] */
    float* s_lse  = s_fm + 32;                /* [32] */
    float* s_Rm   = s_lse + 32;               /* [512] logits warp partials */
    float* s_Rs   = s_Rm + 512;
    int*   s_Ri   = (int*)(s_Rs + 512);
    float* s_w    = (float*)(s_Ri + 512);     /* [2 halves][3 bufs][128*WST] */

    int tid = threadIdx.x, blk = blockIdx.x;
    int w = tid >> 5, lane = tid & 31;
    int half = tid >> 8, th = tid & 255;
    int tile = blk + 128 * half;
    bool act = (tile < NTILE);
    int vb = tile * 128;

    /* ================= pre phase ================= */
    { int i = blk * NT + tid;
      if (i < B * H) { g_h0[0][i] = 0.f; g_h0[1][i] = 0.f; g_c0[i] = 0.f;
                       g_h1[0][i] = 0.f; g_h1[1][i] = 0.f; g_c1[i] = 0.f; } }
    if (blk == 0 && tid < 64) ((u64*)g_amax)[tid] = 0ull;   /* key 0 < any real key */
    for (int i = tid; i < B * 512; i += NT) {
        int b = i >> 9, k = i & 511;
        s_x[b * XPAD + k] = ctx[i];
    }
    __syncthreads();
    { int r = blk * 16 + w;
      const ulonglong2* wp = (const ulonglong2*)(Wih0 + (size_t)r * 1024 + 512);
      const ulonglong2* xp = (const ulonglong2*)(s_x + lane * XPAD);
      u64 a0 = 0, a1 = 0;
#pragma unroll 4
      for (int q = 0; q < 128; q++) {
          ulonglong2 a = wp[q], x = xp[q];
          fma2(a0, a.x, x.x); fma2(a1, a.y, x.y);
      }
      g_pre0[r * 32 + lane] = (f2sum(a0) + f2sum(a1)) + bih0[r] + bhh0[r];
    }
    gridbar();

    /* ================= decode loop ================= */
    for (int t = 0; t <= T; t++) {
        /* ---- prologue ---- */
        if (t > 0) {
            if (tid < 32) {
                u64 key = g_amax[(t - 1) & 1][tid];
                s_tok[tid] = (int)(~(unsigned)(key & 0xffffffffu));
                s_fm[tid]  = funsort((unsigned)(key >> 32));
            }
            __syncthreads();
            if (blk < 8) {      /* deterministic distributed LSE partials */
                int b = lane, g = w;
                float mb = s_fm[b];
                float s = 0.0f;
#pragma unroll
                for (int k = 0; k < 2; k++) {
                    int p = blk * 32 + g + 16 * k;
                    if (p < NTILE)
                        s += g_psum[p * 32 + b] * expf(g_pmax[p * 32 + b] - mb);
                }
                s_rs[g * 32 + b] = s;
                __syncthreads();
                if (tid < 32) {
                    float s2 = 0.0f;
                    for (int g2 = 0; g2 < 16; g2++) s2 += s_rs[g2 * 32 + tid];
                    g_lsp[blk][tid] = s2;
                }
            }
        } else {
            if (tid < 32) s_tok[tid] = START_INDEX;
            __syncthreads();
        }

        if (t == T) {
            gridbar();          /* publish g_lsp for T-1 */
            if (tid < 32) {
                float s2 = 0.0f;
#pragma unroll
                for (int k = 0; k < 8; k++) s2 += g_lsp[k][tid];
                s_lse[tid] = s_fm[tid] + logf(s2);
            }
            __syncthreads();
            if (act) {
                int b = th >> 3, vl = (th & 7) * 16;
                float lv = s_lse[b];
                float* dst = &out[(size_t)b * ((size_t)T * V) + (size_t)(T - 1) * V
                                  + vb + vl];
#pragma unroll
                for (int c = 0; c < 4; c++) {
                    float4 vv = *(float4*)(dst + 4 * c);
                    vv.x -= lv; vv.y -= lv; vv.z -= lv; vv.w -= lv;
                    __stcs((float4*)(dst + 4 * c), vv);
                }
            }
            break;
        }

        /* ---- early Wout prefetch (no dependencies): chunks 0,1 ---- */
        if (act) pf_chunk(s_w, half, 0, Wout, vb, 0, th);
        CP_COMMIT();
        if (act) pf_chunk(s_w, half, 1, Wout, vb, 1, th);
        CP_COMMIT();

        int prev = t & 1, nxt = prev ^ 1;
        int rq = w >> 2, kq = w & 3, j0 = blk * 4;

        /* ---- lstm0 ---- */
        for (int i = tid; i < 32 * 128; i += NT) {
            int b = i >> 7, q = i & 127;
            *(float4*)(s_x + b * XPAD + 4 * q) =
                __ldcs((const float4*)(emb + (size_t)s_tok[b] * 512 + 4 * q));
        }
        __syncthreads();
        {
            u64 acc[4] = {0, 0, 0, 0};
            gemm4(acc, Wih0 + (size_t)(rq * 512 + j0) * 1024, 256, s_x, kq, lane);
            __syncthreads();
            for (int i = tid; i < 32 * 128; i += NT) {
                int b = i >> 7, q = i & 127;
                *(float4*)(s_x + b * XPAD + 4 * q) =
                    *(const float4*)(&g_h0[prev][b * 512 + 4 * q]);
            }
            __syncthreads();
            gemm4(acc, Whh0 + (size_t)(rq * 512 + j0) * 512, 128, s_x, kq, lane);
#pragma unroll
            for (int j = 0; j < 4; j++)
                s_p[(kq * 16 + rq * 4 + j) * 32 + lane] = f2sum(acc[j]);
            __syncthreads();
            if (tid < 128) {
                int jl = tid >> 5, b = tid & 31;
                int jg = j0 + jl;
                float gs[4];
#pragma unroll
                for (int g = 0; g < 4; g++) {
                    float s = 0.0f;
#pragma unroll
                    for (int k = 0; k < 4; k++) s += s_p[(k * 16 + g * 4 + jl) * 32 + b];
                    gs[g] = s + g_pre0[(g * 512 + jg) * 32 + b];
                }
                float c  = g_c0[b * 512 + jg];
                float cn = sigf(gs[1]) * c + sigf(gs[0]) * tanhf(gs[2]);
                float hn = sigf(gs[3]) * tanhf(cn);
                g_c0[b * 512 + jg] = cn;
                g_h0[nxt][b * 512 + jg] = hn;
            }
        }
        gridbar();

        /* reset amax parity consumed this prologue */
        if (blk == 0 && tid < 32) g_amax[(t - 1) & 1][tid] = 0ull;

        /* ---- lstm1 ---- */
        for (int i = tid; i < 32 * 128; i += NT) {
            int b = i >> 7, q = i & 127;
            *(float4*)(s_x + b * XPAD + 4 * q) =
                *(const float4*)(&g_h0[nxt][b * 512 + 4 * q]);
        }
        __syncthreads();
        {
            u64 acc[4] = {0, 0, 0, 0};
            gemm4(acc, Wih1 + (size_t)(rq * 512 + j0) * 512, 128, s_x, kq, lane);
            __syncthreads();
            for (int i = tid; i < 32 * 128; i += NT) {
                int b = i >> 7, q = i & 127;
                *(float4*)(s_x + b * XPAD + 4 * q) =
                    *(const float4*)(&g_h1[prev][b * 512 + 4 * q]);
            }
            __syncthreads();
            gemm4(acc, Whh1 + (size_t)(rq * 512 + j0) * 512, 128, s_x, kq, lane);
#pragma unroll
            for (int j = 0; j < 4; j++)
                s_p[(kq * 16 + rq * 4 + j) * 32 + lane] = f2sum(acc[j]);
            __syncthreads();
            if (tid < 128) {
                int jl = tid >> 5, b = tid & 31;
                int jg = j0 + jl;
                float gs[4];
#pragma unroll
                for (int g = 0; g < 4; g++) {
                    float s = 0.0f;
#pragma unroll
                    for (int k = 0; k < 4; k++) s += s_p[(k * 16 + g * 4 + jl) * 32 + b];
                    int rr = g * 512 + jg;
                    gs[g] = s + bih1[rr] + bhh1[rr];
                }
                float c  = g_c1[b * 512 + jg];
                float cn = sigf(gs[1]) * c + sigf(gs[0]) * tanhf(gs[2]);
                float hn = sigf(gs[3]) * tanhf(cn);
                g_c1[b * 512 + jg] = cn;
                g_h1[nxt][b * 512 + jg] = hn;
            }
        }
        gridbar();

        /* ---- logits: smem-staged Wout, 3-stage cp.async, per-half barriers */
        for (int i = tid; i < 32 * 128; i += NT) {
            int b = i >> 7, q = i & 127;
            *(float4*)(s_x + b * XPAD + 4 * q) =
                *(const float4*)(&g_h1[nxt][b * 512 + 4 * q]);
        }
        if (t > 0 && tid < 32) {
            float s2 = 0.0f;
#pragma unroll
            for (int k = 0; k < 8; k++) s2 += g_lsp[k][tid];
            s_lse[tid] = s_fm[tid] + logf(s2);
        }
        __syncthreads();

        int vg = th >> 3, bg = th & 7;       /* thread tile 4v x 4b */
        float l[4][4];
        u64 a[4][4];
#pragma unroll
        for (int j = 0; j < 4; j++)
#pragma unroll
            for (int i = 0; i < 4; i++) a[j][i] = 0;

        for (int c = 0; c < NCHK; c++) {
            CP_WAIT1();                      /* chunk c resident */
            BARH(half + 1);                  /* half-wide visibility */
            if (act && c + 2 < NCHK)
                pf_chunk(s_w, half, (c + 2) % 3, Wout, vb, c + 2, th);
            CP_COMMIT();
            if (act) {
                const float* wt = s_w + (half * 3 + (c % 3)) * (128 * WST);
#pragma unroll
                for (int qm = 0; qm < 8; qm++) {
                    int q = c * 8 + qm;
                    ulonglong2 hv[4], wv[4];
#pragma unroll
                    for (int i = 0; i < 4; i++)
                        hv[i] = *(const ulonglong2*)(s_x + (bg + 8 * i) * XPAD + 4 * q);
#pragma unroll
                    for (int j = 0; j < 4; j++)
                        wv[j] = *(const ulonglong2*)(wt + (vg + 32 * j) * WST + qm * 4);
#pragma unroll
                    for (int j = 0; j < 4; j++)
#pragma unroll
                        for (int i = 0; i < 4; i++) {
                            fma2(a[j][i], wv[j].x, hv[i].x);
                            fma2(a[j][i], wv[j].y, hv[i].y);
                        }
                }
            }
        }

        if (act) {
            float bj[4];
#pragma unroll
            for (int j = 0; j < 4; j++) bj[j] = bout[vb + vg + 32 * j];

            int lw = th & 31;
#pragma unroll
            for (int i = 0; i < 4; i++) {
                float m = -3.0e38f; int mi = 0;
#pragma unroll
                for (int j = 0; j < 4; j++) {
                    float lv = f2sum(a[j][i]) + bj[j];
                    l[i][j] = lv;
                    if (lv > m) { m = lv; mi = vb + vg + 32 * j; }
                }
                float s = 0.f;
#pragma unroll
                for (int j = 0; j < 4; j++) s += expf(l[i][j] - m);
#pragma unroll
                for (int off = 8; off <= 16; off <<= 1) {
                    float om = __shfl_xor_sync(0xffffffffu, m, off);
                    float os = __shfl_xor_sync(0xffffffffu, s, off);
                    int   oi = __shfl_xor_sync(0xffffffffu, mi, off);
                    comb(m, s, mi, om, os, oi);
                }
                if (lw < 8) {
                    int idx = half * 256 + (th >> 5) * 32 + bg * 4 + i;
                    s_Rm[idx] = m; s_Rs[idx] = s; s_Ri[idx] = mi;
                }
            }
        }
        __syncthreads();                     /* s_x free for overlay */

        float* s_ov = s_x + half * 4224;     /* [32][132] per half */
        if (act) {
#pragma unroll
            for (int i = 0; i < 4; i++)
#pragma unroll
                for (int j = 0; j < 4; j++)
                    s_ov[(bg + 8 * i) * 132 + vg + 32 * j] = l[i][j];
        }
        if (tid < 64) {                      /* per-tile combine + global argmax */
            int tl = tid >> 5, b = tid & 31;
            int t2 = blk + 128 * tl;
            if (t2 < NTILE) {
                int bg2 = b & 7, i2 = b >> 3;
                float m = -3.0e38f, s = 0.f; int mi = 0x7fffffff;
                for (int w2 = 0; w2 < 8; w2++) {
                    int idx = tl * 256 + w2 * 32 + bg2 * 4 + i2;
                    comb(m, s, mi, s_Rm[idx], s_Rs[idx], s_Ri[idx]);
                }
                g_pmax[t2 * 32 + b] = m;
                g_psum[t2 * 32 + b] = s;
                atomicMax(&g_amax[t & 1][b], packkey(m, mi));
            }
        }
        __syncthreads();

        if (act) {
            int b = th >> 3, vl = (th & 7) * 16;
            const float* src = s_ov + b * 132 + vl;
            float* dst = &out[(size_t)b * ((size_t)T * V) + (size_t)t * V + vb + vl];
#pragma unroll
            for (int c = 0; c < 4; c++)
                __stcs((float4*)(dst + 4 * c), *(const float4*)(src + 4 * c));
            if (t > 0) {                     /* normalize own tile of step t-1 */
                float lv = s_lse[b];
                float* pd = &out[(size_t)b * ((size_t)T * V) + (size_t)(t - 1) * V + vb + vl];
#pragma unroll
                for (int c = 0; c < 4; c++) {
                    float4 vv = __ldcs((const float4*)(pd + 4 * c));
                    vv.x -= lv; vv.y -= lv; vv.z -= lv; vv.w -= lv;
                    __stcs((float4*)(pd + 4 * c), vv);
                }
            }
        }
        gridbar();
    }
}

/* -------------------------------- launch ---------------------------------- */
#define SMEM_ALL ((32 * XPAD + 2048 + 512 + 32 * 3 + 512 * 3 + 6 * 128 * WST) * 4)

extern "C" void kernel_launch(void* const* d_in, const int* in_sizes, int n_in,
                              void* d_out, int out_size) {
    const float* ctx  = (const float*)d_in[0];
    const float* emb  = (const float*)d_in[1];
    const float* Wih0 = (const float*)d_in[2];
    const float* Whh0 = (const float*)d_in[3];
    const float* bih0 = (const float*)d_in[4];
    const float* bhh0 = (const float*)d_in[5];
    const float* Wih1 = (const float*)d_in[6];
    const float* Whh1 = (const float*)d_in[7];
    const float* bih1 = (const float*)d_in[8];
    const float* bhh1 = (const float*)d_in[9];
    const float* Wout = (const float*)d_in[10];
    const float* bout = (const float*)d_in[11];
    float* out = (float*)d_out;

    cudaFuncSetAttribute(k_all, cudaFuncAttributeMaxDynamicSharedMemorySize, SMEM_ALL);
    k_all<<<GRID, NT, SMEM_ALL>>>(ctx, emb, Wih0, Whh0, bih0, bhh0,
                                  Wih1, Whh1, bih1, bhh1, Wout, bout, out);
}

// round 15
// speedup vs baseline: 1.2988x; 1.1305x over previous
#include <cuda_runtime.h>
#include <math.h>
#include <stddef.h>

#define B 32
#define H 512
#define V 32000
#define T 64
#define GRID 128
#define NT 512
#define NTILE 250           /* 250 logits tiles of 128 vocab rows */
#define START_INDEX 1
#define XPAD 516            /* conflict-free 16B smem reads, lane = batch */
#define NCHK 16             /* logits k-chunks: 8 q (32 floats) each */
#define WST 36              /* padded floats per row per chunk buffer */

typedef unsigned long long u64;

/* ------------------------- persistent device scratch ---------------------- */
__device__ float g_h0[2][B * H];
__device__ float g_c0[B * H];
__device__ float g_h1[2][B * H];
__device__ float g_c1[B * H];
__device__ float g_pre0[2048 * B];  /* ctx part of layer0 gates + b_ih + b_hh */
__device__ float g_pmax[NTILE * B];
__device__ float g_psum[NTILE * B];
__device__ u64   g_amax[2][B];      /* packed (sortable(max)<<32)|~idx, per parity */
__device__ float g_lsp[8][B];       /* distributed deterministic LSE partials */
__device__ int          g_cnt[16];  /* two-level barrier */
__device__ int          g_cnt_root;
__device__ volatile int g_gen;

__device__ __forceinline__ float sigf(float x) { return 1.0f / (1.0f + expf(-x)); }

/* packed fp32x2 FMA: d.lo += a.lo*b.lo ; d.hi += a.hi*b.hi */
__device__ __forceinline__ void fma2(u64& d, u64 a, u64 b) {
    asm("fma.rn.f32x2 %0, %1, %2, %0;" : "+l"(d) : "l"(a), "l"(b));
}
union F2U { u64 u; float2 f; };
__device__ __forceinline__ float f2sum(u64 v) { F2U t; t.u = v; return t.f.x + t.f.y; }

/* order-preserving float<->u32 transform */
__device__ __forceinline__ unsigned fsort(float x) {
    unsigned u = __float_as_uint(x);
    return u ^ ((unsigned)(((int)u) >> 31) | 0x80000000u);
}
__device__ __forceinline__ float funsort(unsigned s) {
    unsigned u = (s & 0x80000000u) ? (s ^ 0x80000000u) : ~s;
    return __uint_as_float(u);
}
__device__ __forceinline__ u64 packkey(float m, int idx) {
    return ((u64)fsort(m) << 32) | (u64)(~(unsigned)idx);
}

/* cp.async 16B, L1-bypass (.cg): GMEM -> SMEM without touching L1 */
__device__ __forceinline__ void cpa16(void* dst, const void* src) {
    unsigned d = (unsigned)__cvta_generic_to_shared(dst);
    asm volatile("cp.async.cg.shared.global [%0], [%1], 16;" :: "r"(d), "l"(src));
}
#define CP_COMMIT() asm volatile("cp.async.commit_group;" ::: "memory")
#define CP_WAIT1()  asm volatile("cp.async.wait_group 1;" ::: "memory")
#define CP_WAIT0()  asm volatile("cp.async.wait_group 0;" ::: "memory")
#define BARH(id)    asm volatile("bar.sync %0, %1;" :: "r"(id), "r"(256) : "memory")

/* prefetch one 32-float k-chunk of a 128-row Wout tile into buffer buf */
__device__ __forceinline__ void pf_chunk(float* s_w, int half, int buf,
                                         const float* Wout, int vb, int c, int th) {
#pragma unroll
    for (int k = 0; k < 4; k++) {
        int o = th + 256 * k;               /* 0..1023 */
        int r = o >> 3, s = o & 7;
        cpa16(s_w + (half * 3 + buf) * (128 * WST) + r * WST + s * 4,
              Wout + (size_t)(vb + r) * 512 + c * 32 + s * 4);
    }
}

/* grid barrier, two-level arrivals; replay-safe; all GRID blocks co-resident */
__device__ __forceinline__ void gridbar() {
    __syncthreads();
    if (threadIdx.x == 0) {
        int gen = g_gen;
        __threadfence();
        if (atomicAdd(&g_cnt[blockIdx.x >> 3], 1) == 7) {
            g_cnt[blockIdx.x >> 3] = 0;
            if (atomicAdd(&g_cnt_root, 1) == 15) {
                g_cnt_root = 0;
                __threadfence();
                g_gen = gen + 1;
            }
        }
        while (g_gen == gen) __nanosleep(32);
        __threadfence();
    }
    __syncthreads();
}

/* 4-row GEMM slice: acc[j] += W[row j][k-quarter] . x  (rows rs_u2 u2 apart).
 * W may point to global or shared (uniform address across the warp). */
__device__ __forceinline__ void gemm4(u64* acc, const float* W, int rs_u2,
                                      const float* s_x, int kq, int lane) {
    const ulonglong2* xp = (const ulonglong2*)(s_x + lane * XPAD);
    const ulonglong2* wp = (const ulonglong2*)W;
#pragma unroll 4
    for (int q = kq * 32; q < kq * 32 + 32; q++) {
        ulonglong2 xv = xp[q];
        ulonglong2 w0 = wp[q], w1 = wp[rs_u2 + q], w2 = wp[2 * rs_u2 + q], w3 = wp[3 * rs_u2 + q];
        fma2(acc[0], w0.x, xv.x); fma2(acc[0], w0.y, xv.y);
        fma2(acc[1], w1.x, xv.x); fma2(acc[1], w1.y, xv.y);
        fma2(acc[2], w2.x, xv.x); fma2(acc[2], w2.y, xv.y);
        fma2(acc[3], w3.x, xv.x); fma2(acc[3], w3.y, xv.y);
    }
}

/* combine (m,s,idx) softmax partials; first-index tie rule */
__device__ __forceinline__ void comb(float& m, float& s, int& mi,
                                     float om, float os, int oi) {
    if (om > m || (om == m && oi < mi)) { s = s * expf(m - om) + os; m = om; mi = oi; }
    else                                { s += os * expf(om - m); }
}

/* ---------------------------------------------------------------------------
 * Whole decode, one persistent kernel. 128 blocks x 512 threads.
 * ------------------------------------------------------------------------- */
__global__ __launch_bounds__(NT) void k_all(
    const float* __restrict__ ctx,  const float* __restrict__ emb,
    const float* __restrict__ Wih0, const float* __restrict__ Whh0,
    const float* __restrict__ bih0, const float* __restrict__ bhh0,
    const float* __restrict__ Wih1, const float* __restrict__ Whh1,
    const float* __restrict__ bih1, const float* __restrict__ bhh1,
    const float* __restrict__ Wout, const float* __restrict__ bout,
    float* __restrict__ out)
{
    extern __shared__ float sm[];
    float* s_x    = sm;                       /* [32][XPAD] 16512 fl (also store overlay) */
    float* s_p    = s_x + 32 * XPAD;          /* [4][16][32] LSTM partials */
    float* s_rs   = s_p + 2048;               /* [16][32] LSE partial reduce */
    int*   s_tok  = (int*)(s_rs + 512);       /* [32] */
    float* s_fm   = (float*)(s_tok + 32);     /* [32] */
    float* s_lse  = s_fm + 32;                /* [32] */
    float* s_Rm   = s_lse + 32;               /* [512] logits warp partials */
    float* s_Rs   = s_Rm + 512;
    int*   s_Ri   = (int*)(s_Rs + 512);
    float* s_w    = (float*)(s_Ri + 512);     /* 27648 fl: Wout stage / LSTM W stage */

    int tid = threadIdx.x, blk = blockIdx.x;
    int w = tid >> 5, lane = tid & 31;
    int half = tid >> 8, th = tid & 255;
    int tile = blk + 128 * half;
    bool act = (tile < NTILE);
    int vb = tile * 128;
    int j0 = blk * 4;

    /* ================= pre phase ================= */
    { int i = blk * NT + tid;
      if (i < B * H) { g_h0[0][i] = 0.f; g_h0[1][i] = 0.f; g_c0[i] = 0.f;
                       g_h1[0][i] = 0.f; g_h1[1][i] = 0.f; g_c1[i] = 0.f; } }
    if (blk == 0 && tid < 64) ((u64*)g_amax)[tid] = 0ull;   /* key 0 < any real key */
    for (int i = tid; i < B * 512; i += NT) {
        int b = i >> 9, k = i & 511;
        s_x[b * XPAD + k] = ctx[i];
    }
    __syncthreads();
    { int r = blk * 16 + w;
      const ulonglong2* wp = (const ulonglong2*)(Wih0 + (size_t)r * 1024 + 512);
      const ulonglong2* xp = (const ulonglong2*)(s_x + lane * XPAD);
      u64 a0 = 0, a1 = 0;
#pragma unroll 4
      for (int q = 0; q < 128; q++) {
          ulonglong2 a = wp[q], x = xp[q];
          fma2(a0, a.x, x.x); fma2(a1, a.y, x.y);
      }
      g_pre0[r * 32 + lane] = (f2sum(a0) + f2sum(a1)) + bih0[r] + bhh0[r];
    }
    gridbar();

    /* ================= decode loop ================= */
    for (int t = 0; t <= T; t++) {
        /* ---- prologue ---- */
        if (t > 0) {
            if (tid < 32) {
                u64 key = g_amax[(t - 1) & 1][tid];
                s_tok[tid] = (int)(~(unsigned)(key & 0xffffffffu));
                s_fm[tid]  = funsort((unsigned)(key >> 32));
            }
            __syncthreads();
            if (blk < 8) {      /* deterministic distributed LSE partials */
                int b = lane, g = w;
                float mb = s_fm[b];
                float s = 0.0f;
#pragma unroll
                for (int k = 0; k < 2; k++) {
                    int p = blk * 32 + g + 16 * k;
                    if (p < NTILE)
                        s += g_psum[p * 32 + b] * expf(g_pmax[p * 32 + b] - mb);
                }
                s_rs[g * 32 + b] = s;
                __syncthreads();
                if (tid < 32) {
                    float s2 = 0.0f;
                    for (int g2 = 0; g2 < 16; g2++) s2 += s_rs[g2 * 32 + tid];
                    g_lsp[blk][tid] = s2;
                }
            }
        } else {
            if (tid < 32) s_tok[tid] = START_INDEX;
            __syncthreads();
        }

        if (t == T) {
            gridbar();          /* publish g_lsp for T-1 */
            if (tid < 32) {
                float s2 = 0.0f;
#pragma unroll
                for (int k = 0; k < 8; k++) s2 += g_lsp[k][tid];
                s_lse[tid] = s_fm[tid] + logf(s2);
            }
            __syncthreads();
            if (act) {
                int b = th >> 3, vl = (th & 7) * 16;
                float lv = s_lse[b];
                float* dst = &out[(size_t)b * ((size_t)T * V) + (size_t)(T - 1) * V
                                  + vb + vl];
#pragma unroll
                for (int c = 0; c < 4; c++) {
                    float4 vv = *(float4*)(dst + 4 * c);
                    vv.x -= lv; vv.y -= lv; vv.z -= lv; vv.w -= lv;
                    __stcs((float4*)(dst + 4 * c), vv);
                }
            }
            break;
        }

        /* ---- stage lstm0 weights into smem (96 KB): no dependencies ----
         * W_ih0 slice: 16 rows x 1024 fl = 4096 x 16B; row sr -> 256 chunks.
         * W_hh0 slice: 16 rows x 512 fl  = 2048 x 16B; row sr -> 128 chunks. */
        {
#pragma unroll
            for (int k = 0; k < 8; k++) {
                int o = tid + 512 * k;           /* 0..4095 */
                int sr = o >> 8, c16 = o & 255;
                int gr = (sr >> 2) * 512 + j0 + (sr & 3);
                cpa16(s_w + sr * 1024 + c16 * 4, Wih0 + (size_t)gr * 1024 + c16 * 4);
            }
#pragma unroll
            for (int k = 0; k < 4; k++) {
                int o = tid + 512 * k;           /* 0..2047 */
                int sr = o >> 7, c16 = o & 127;
                int gr = (sr >> 2) * 512 + j0 + (sr & 3);
                cpa16(s_w + 16384 + sr * 512 + c16 * 4, Whh0 + (size_t)gr * 512 + c16 * 4);
            }
            CP_COMMIT();
        }

        int prev = t & 1, nxt = prev ^ 1;
        int rq = w >> 2, kq = w & 3;

        /* ---- lstm0 ---- */
        for (int i = tid; i < 32 * 128; i += NT) {
            int b = i >> 7, q = i & 127;
            *(float4*)(s_x + b * XPAD + 4 * q) =
                __ldcs((const float4*)(emb + (size_t)s_tok[b] * 512 + 4 * q));
        }
        CP_WAIT0();
        __syncthreads();
        {
            u64 acc[4] = {0, 0, 0, 0};
            gemm4(acc, s_w + (rq * 4) * 1024, 256, s_x, kq, lane);
            __syncthreads();
            for (int i = tid; i < 32 * 128; i += NT) {
                int b = i >> 7, q = i & 127;
                *(float4*)(s_x + b * XPAD + 4 * q) =
                    *(const float4*)(&g_h0[prev][b * 512 + 4 * q]);
            }
            __syncthreads();
            gemm4(acc, s_w + 16384 + (rq * 4) * 512, 128, s_x, kq, lane);
#pragma unroll
            for (int j = 0; j < 4; j++)
                s_p[(kq * 16 + rq * 4 + j) * 32 + lane] = f2sum(acc[j]);
            __syncthreads();                     /* all s_w reads done */

            /* stage lstm1 weights (64 KB): 2 slices of 16 rows x 512 fl */
#pragma unroll
            for (int k = 0; k < 4; k++) {
                int o = tid + 512 * k;           /* 0..2047 */
                int sr = o >> 7, c16 = o & 127;
                int gr = (sr >> 2) * 512 + j0 + (sr & 3);
                cpa16(s_w + sr * 512 + c16 * 4, Wih1 + (size_t)gr * 512 + c16 * 4);
            }
#pragma unroll
            for (int k = 0; k < 4; k++) {
                int o = tid + 512 * k;
                int sr = o >> 7, c16 = o & 127;
                int gr = (sr >> 2) * 512 + j0 + (sr & 3);
                cpa16(s_w + 8192 + sr * 512 + c16 * 4, Whh1 + (size_t)gr * 512 + c16 * 4);
            }
            CP_COMMIT();

            if (tid < 128) {
                int jl = tid >> 5, b = tid & 31;
                int jg = j0 + jl;
                float gs[4];
#pragma unroll
                for (int g = 0; g < 4; g++) {
                    float s = 0.0f;
#pragma unroll
                    for (int k = 0; k < 4; k++) s += s_p[(k * 16 + g * 4 + jl) * 32 + b];
                    gs[g] = s + g_pre0[(g * 512 + jg) * 32 + b];
                }
                float c  = g_c0[b * 512 + jg];
                float cn = sigf(gs[1]) * c + sigf(gs[0]) * tanhf(gs[2]);
                float hn = sigf(gs[3]) * tanhf(cn);
                g_c0[b * 512 + jg] = cn;
                g_h0[nxt][b * 512 + jg] = hn;
            }
        }
        gridbar();

        /* reset amax parity consumed this prologue */
        if (blk == 0 && tid < 32) g_amax[(t - 1) & 1][tid] = 0ull;

        /* ---- lstm1 ---- */
        for (int i = tid; i < 32 * 128; i += NT) {
            int b = i >> 7, q = i & 127;
            *(float4*)(s_x + b * XPAD + 4 * q) =
                *(const float4*)(&g_h0[nxt][b * 512 + 4 * q]);
        }
        CP_WAIT0();
        __syncthreads();
        {
            u64 acc[4] = {0, 0, 0, 0};
            gemm4(acc, s_w + (rq * 4) * 512, 128, s_x, kq, lane);
            __syncthreads();
            for (int i = tid; i < 32 * 128; i += NT) {
                int b = i >> 7, q = i & 127;
                *(float4*)(s_x + b * XPAD + 4 * q) =
                    *(const float4*)(&g_h1[prev][b * 512 + 4 * q]);
            }
            __syncthreads();
            gemm4(acc, s_w + 8192 + (rq * 4) * 512, 128, s_x, kq, lane);
#pragma unroll
            for (int j = 0; j < 4; j++)
                s_p[(kq * 16 + rq * 4 + j) * 32 + lane] = f2sum(acc[j]);
            __syncthreads();                     /* all s_w reads done */

            /* Wout chunks 0,1 prefetch — overlaps gate math + barrier */
            if (act) pf_chunk(s_w, half, 0, Wout, vb, 0, th);
            CP_COMMIT();
            if (act) pf_chunk(s_w, half, 1, Wout, vb, 1, th);
            CP_COMMIT();

            if (tid < 128) {
                int jl = tid >> 5, b = tid & 31;
                int jg = j0 + jl;
                float gs[4];
#pragma unroll
                for (int g = 0; g < 4; g++) {
                    float s = 0.0f;
#pragma unroll
                    for (int k = 0; k < 4; k++) s += s_p[(k * 16 + g * 4 + jl) * 32 + b];
                    int rr = g * 512 + jg;
                    gs[g] = s + bih1[rr] + bhh1[rr];
                }
                float c  = g_c1[b * 512 + jg];
                float cn = sigf(gs[1]) * c + sigf(gs[0]) * tanhf(gs[2]);
                float hn = sigf(gs[3]) * tanhf(cn);
                g_c1[b * 512 + jg] = cn;
                g_h1[nxt][b * 512 + jg] = hn;
            }
        }
        gridbar();

        /* ---- logits: smem-staged Wout, 3-stage cp.async, per-half barriers */
        for (int i = tid; i < 32 * 128; i += NT) {
            int b = i >> 7, q = i & 127;
            *(float4*)(s_x + b * XPAD + 4 * q) =
                *(const float4*)(&g_h1[nxt][b * 512 + 4 * q]);
        }
        if (t > 0 && tid < 32) {
            float s2 = 0.0f;
#pragma unroll
            for (int k = 0; k < 8; k++) s2 += g_lsp[k][tid];
            s_lse[tid] = s_fm[tid] + logf(s2);
        }
        __syncthreads();

        int vg = th >> 3, bg = th & 7;       /* thread tile 4v x 4b */
        float l[4][4];
        u64 a[4][4];
#pragma unroll
        for (int j = 0; j < 4; j++)
#pragma unroll
            for (int i = 0; i < 4; i++) a[j][i] = 0;

        for (int c = 0; c < NCHK; c++) {
            CP_WAIT1();                      /* chunk c resident */
            BARH(half + 1);                  /* half-wide visibility */
            if (act && c + 2 < NCHK)
                pf_chunk(s_w, half, (c + 2) % 3, Wout, vb, c + 2, th);
            CP_COMMIT();
            if (act) {
                const float* wt = s_w + (half * 3 + (c % 3)) * (128 * WST);
#pragma unroll
                for (int qm = 0; qm < 8; qm++) {
                    int q = c * 8 + qm;
                    ulonglong2 hv[4], wv[4];
#pragma unroll
                    for (int i = 0; i < 4; i++)
                        hv[i] = *(const ulonglong2*)(s_x + (bg + 8 * i) * XPAD + 4 * q);
#pragma unroll
                    for (int j = 0; j < 4; j++)
                        wv[j] = *(const ulonglong2*)(wt + (vg + 32 * j) * WST + qm * 4);
#pragma unroll
                    for (int j = 0; j < 4; j++)
#pragma unroll
                        for (int i = 0; i < 4; i++) {
                            fma2(a[j][i], wv[j].x, hv[i].x);
                            fma2(a[j][i], wv[j].y, hv[i].y);
                        }
                }
            }
        }

        if (act) {
            float bj[4];
#pragma unroll
            for (int j = 0; j < 4; j++) bj[j] = bout[vb + vg + 32 * j];

            int lw = th & 31;
#pragma unroll
            for (int i = 0; i < 4; i++) {
                float m = -3.0e38f; int mi = 0;
#pragma unroll
                for (int j = 0; j < 4; j++) {
                    float lv = f2sum(a[j][i]) + bj[j];
                    l[i][j] = lv;
                    if (lv > m) { m = lv; mi = vb + vg + 32 * j; }
                }
                float s = 0.f;
#pragma unroll
                for (int j = 0; j < 4; j++) s += expf(l[i][j] - m);
#pragma unroll
                for (int off = 8; off <= 16; off <<= 1) {
                    float om = __shfl_xor_sync(0xffffffffu, m, off);
                    float os = __shfl_xor_sync(0xffffffffu, s, off);
                    int   oi = __shfl_xor_sync(0xffffffffu, mi, off);
                    comb(m, s, mi, om, os, oi);
                }
                if (lw < 8) {
                    int idx = half * 256 + (th >> 5) * 32 + bg * 4 + i;
                    s_Rm[idx] = m; s_Rs[idx] = s; s_Ri[idx] = mi;
                }
            }
        }
        __syncthreads();                     /* s_x free for overlay */

        float* s_ov = s_x + half * 4224;     /* [32][132] per half */
        if (act) {
#pragma unroll
            for (int i = 0; i < 4; i++)
#pragma unroll
                for (int j = 0; j < 4; j++)
                    s_ov[(bg + 8 * i) * 132 + vg + 32 * j] = l[i][j];
        }
        if (tid < 64) {                      /* per-tile combine + global argmax */
            int tl = tid >> 5, b = tid & 31;
            int t2 = blk + 128 * tl;
            if (t2 < NTILE) {
                int bg2 = b & 7, i2 = b >> 3;
                float m = -3.0e38f, s = 0.f; int mi = 0x7fffffff;
                for (int w2 = 0; w2 < 8; w2++) {
                    int idx = tl * 256 + w2 * 32 + bg2 * 4 + i2;
                    comb(m, s, mi, s_Rm[idx], s_Rs[idx], s_Ri[idx]);
                }
                g_pmax[t2 * 32 + b] = m;
                g_psum[t2 * 32 + b] = s;
                atomicMax(&g_amax[t & 1][b], packkey(m, mi));
            }
        }
        __syncthreads();

        if (act) {
            int b = th >> 3, vl = (th & 7) * 16;
            const float* src = s_ov + b * 132 + vl;
            float* dst = &out[(size_t)b * ((size_t)T * V) + (size_t)t * V + vb + vl];
#pragma unroll
            for (int c = 0; c < 4; c++)
                __stcs((float4*)(dst + 4 * c), *(const float4*)(src + 4 * c));
            if (t > 0) {                     /* normalize own tile of step t-1 */
                float lv = s_lse[b];
                float* pd = &out[(size_t)b * ((size_t)T * V) + (size_t)(t - 1) * V + vb + vl];
#pragma unroll
                for (int c = 0; c < 4; c++) {
                    float4 vv = __ldcs((const float4*)(pd + 4 * c));
                    vv.x -= lv; vv.y -= lv; vv.z -= lv; vv.w -= lv;
                    __stcs((float4*)(pd + 4 * c), vv);
                }
            }
        }
        gridbar();
    }
}

/* -------------------------------- launch ---------------------------------- */
#define SMEM_ALL ((32 * XPAD + 2048 + 512 + 32 * 3 + 512 * 3 + 6 * 128 * WST) * 4)

extern "C" void kernel_launch(void* const* d_in, const int* in_sizes, int n_in,
                              void* d_out, int out_size) {
    const float* ctx  = (const float*)d_in[0];
    const float* emb  = (const float*)d_in[1];
    const float* Wih0 = (const float*)d_in[2];
    const float* Whh0 = (const float*)d_in[3];
    const float* bih0 = (const float*)d_in[4];
    const float* bhh0 = (const float*)d_in[5];
    const float* Wih1 = (const float*)d_in[6];
    const float* Whh1 = (const float*)d_in[7];
    const float* bih1 = (const float*)d_in[8];
    const float* bhh1 = (const float*)d_in[9];
    const float* Wout = (const float*)d_in[10];
    const float* bout = (const float*)d_in[11];
    float* out = (float*)d_out;

    cudaFuncSetAttribute(k_all, cudaFuncAttributeMaxDynamicSharedMemorySize, SMEM_ALL);
    k_all<<<GRID, NT, SMEM_ALL>>>(ctx, emb, Wih0, Whh0, bih0, bhh0,
                                  Wih1, Whh1, bih1, bhh1, Wout, bout, out);
}